// round 11
// baseline (speedup 1.0000x reference)
#include <cuda_runtime.h>
#include <cuda_fp16.h>
#include <cstdint>

// ---------------------------------------------------------------------------
// Problem constants
// ---------------------------------------------------------------------------
#define BT     16384          // B*T tokens
#define DOUT   256
#define K0     300
#define K1     300
#define K2     200
#define KTOT   800
#define KPAD   832            // 13 * 64, zero padded
#define NCHUNK 13

// Fused GEMM tiling
#define BM 128
#define BN 256
#define STAGES 3
#define SPITCH 72                        // fp16 elems per smem row (64 + 8 pad)
#define A_STAGE (BM * SPITCH * 2)        // 18432 B
#define B_STAGE (BN * SPITCH * 2)        // 36864 B
#define DYN_SMEM (STAGES * (A_STAGE + B_STAGE))   // 165888 B

// ---------------------------------------------------------------------------
// Device-global scratch
// ---------------------------------------------------------------------------
__device__ float g_u[KTOT];
__device__ float g_c[3];
__device__ __align__(16) __half g_Wh[(size_t)DOUT * KPAD];   // [n][k] (W transposed), fp16

// ---------------------------------------------------------------------------
// Helpers
// ---------------------------------------------------------------------------
__device__ __forceinline__ uint32_t su32(const void* p) {
    uint32_t a;
    asm("{ .reg .u64 t; cvta.to.shared.u64 t, %1; cvt.u32.u64 %0, t; }" : "=r"(a) : "l"(p));
    return a;
}
__device__ __forceinline__ void cpa16(uint32_t dst, const void* src) {
    asm volatile("cp.async.cg.shared.global [%0], [%1], 16;" :: "r"(dst), "l"(src) : "memory");
}
#define LDSM4(r, addr) \
    asm volatile("ldmatrix.sync.aligned.m8n8.x4.shared.b16 {%0,%1,%2,%3}, [%4];" \
                 : "=r"((r)[0]), "=r"((r)[1]), "=r"((r)[2]), "=r"((r)[3]) : "r"(addr))
#define MMA16816(d, a, bb0, bb1) \
    asm volatile("mma.sync.aligned.m16n8k16.row.col.f32.f16.f16.f32 " \
                 "{%0,%1,%2,%3}, {%4,%5,%6,%7}, {%8,%9}, {%0,%1,%2,%3};" \
                 : "+f"((d)[0]), "+f"((d)[1]), "+f"((d)[2]), "+f"((d)[3]) \
                 : "r"((a)[0]), "r"((a)[1]), "r"((a)[2]), "r"((a)[3]), "r"(bb0), "r"(bb1))

__device__ __forceinline__ uint32_t pack_h2(float v0, float v1) {
    __half2 h = __floats2half2_rn(v0, v1);
    return *reinterpret_cast<uint32_t*>(&h);
}

// ---------------------------------------------------------------------------
// Kernel 1 (unchanged, known-good): u = concat(W)@Wa, c = b.Wa + ba,
// W -> Wh^T fp16.  blocks [0,104): prep.  blocks [104,520): W convert.
// ---------------------------------------------------------------------------
__global__ void prepw_kernel(const float* __restrict__ W0, const float* __restrict__ b0,
                             const float* __restrict__ W1, const float* __restrict__ b1,
                             const float* __restrict__ W2, const float* __restrict__ b2,
                             const float* __restrict__ Wa, const float* __restrict__ ba)
{
    const int tid = threadIdx.x;
    if (blockIdx.x < 104) {
        int warp = blockIdx.x * 8 + (tid >> 5);
        int lane = tid & 31;
        if (warp < KTOT) {
            const float* row;
            if (warp < K0)           row = W0 + (size_t)warp * DOUT;
            else if (warp < K0+K1)   row = W1 + (size_t)(warp - K0) * DOUT;
            else                     row = W2 + (size_t)(warp - K0 - K1) * DOUT;
            float s = 0.f;
            for (int d = lane; d < DOUT; d += 32) s += row[d] * Wa[d];
            #pragma unroll
            for (int o = 16; o; o >>= 1) s += __shfl_xor_sync(0xffffffffu, s, o);
            if (lane == 0) g_u[warp] = s;
        } else if (warp < KTOT + 3) {
            int n = warp - KTOT;
            const float* b = (n == 0) ? b0 : ((n == 1) ? b1 : b2);
            float s = 0.f;
            for (int d = lane; d < DOUT; d += 32) s += b[d] * Wa[d];
            #pragma unroll
            for (int o = 16; o; o >>= 1) s += __shfl_xor_sync(0xffffffffu, s, o);
            if (lane == 0) g_c[n] = s + ba[0];
        }
    } else {
        int idx = (blockIdx.x - 104) * 256 + tid;
        if (idx < DOUT * (KPAD/2)) {
            int n  = idx / (KPAD/2);
            int k  = (idx % (KPAD/2)) * 2;
            float v0 = 0.f, v1 = 0.f;
            if (k < K0)        { v0 = W0[(size_t)k*DOUT + n];       v1 = W0[(size_t)(k+1)*DOUT + n]; }
            else if (k < 600)  { v0 = W1[(size_t)(k-300)*DOUT + n]; v1 = W1[(size_t)(k-299)*DOUT + n]; }
            else if (k < 800)  { v0 = W2[(size_t)(k-600)*DOUT + n]; v1 = W2[(size_t)(k-599)*DOUT + n]; }
            size_t off = ((size_t)n * KPAD + k) * 2;
            *(uint32_t*)((char*)g_Wh + off) = pack_h2(v0, v1);
        }
    }
}

// ---------------------------------------------------------------------------
// Kernel 2 (fused): per CTA of 128 tokens x all 256 outputs.
// Phase 1: logits + softmax (E from DRAM).  Mainloop: A produced in-kernel
// (E from L2, alpha-scaled, fp16), B via cp.async of g_Wh, 3-stage, HMMA.
// ---------------------------------------------------------------------------
__global__ void __launch_bounds__(512, 1)
fused_kernel(const int* __restrict__ ids,
             const float* __restrict__ E0, const float* __restrict__ E1,
             const float* __restrict__ E2,
             const float* __restrict__ b0, const float* __restrict__ b1,
             const float* __restrict__ b2, float* __restrict__ out)
{
    extern __shared__ __align__(16) __half dyn[];
    __shared__ float su[KTOT];
    __shared__ float sc3[3];
    __shared__ float sAlpha[3][BM];
    __shared__ float sBias[3][BN];
    __shared__ int   sIds[BM];

    const int tid  = threadIdx.x;
    const int wid  = tid >> 5;
    const int lane = tid & 31;
    const int m0   = blockIdx.x * BM;

    const uint32_t sb  = su32(dyn);
    const uint32_t sbB = sb + STAGES * A_STAGE;

    for (int i = tid; i < KTOT; i += 512) su[i] = g_u[i];
    if (tid < 3) sc3[tid] = g_c[tid];
    for (int i = tid; i < BN; i += 512) {
        sBias[0][i] = b0[i];
        sBias[1][i] = b1[i];
        sBias[2][i] = b2[i];
    }
    if (tid < BM) sIds[tid] = ids[m0 + tid];
    __syncthreads();

    // ---- B prefetch for chunks 0,1 (independent of phase 1) ----
    auto loadB = [&](int c, int stage) {
        const char* Bg = (const char*)g_Wh + c * 128;
        const uint32_t Bs = sbB + stage * B_STAGE;
        #pragma unroll
        for (int i = 0; i < 4; i++) {
            int idx = tid + i * 512;
            int row = idx >> 3, cc = idx & 7;
            cpa16(Bs + (row * SPITCH + cc * 8) * 2, Bg + (size_t)row * (KPAD*2) + cc * 16);
        }
        asm volatile("cp.async.commit_group;" ::: "memory");
    };
    loadB(0, 0);
    loadB(1, 1);

    // ---- phase 1: logits + softmax; warp w handles tokens w*8..w*8+7 ----
    #pragma unroll 1
    for (int j = 0; j < 8; j++) {
        const int t = wid * 8 + j;
        const size_t id = (size_t)sIds[t];
        const float* r0 = E0 + id * K0;
        const float* r1 = E1 + id * K1;
        const float* r2 = E2 + id * K2;
        float l0 = 0.f, l1 = 0.f, l2 = 0.f;
        for (int k = lane; k < K0; k += 32) l0 += r0[k] * su[k];
        for (int k = lane; k < K1; k += 32) l1 += r1[k] * su[K0 + k];
        for (int k = lane; k < K2; k += 32) l2 += r2[k] * su[K0 + K1 + k];
        #pragma unroll
        for (int o = 16; o; o >>= 1) {
            l0 += __shfl_xor_sync(0xffffffffu, l0, o);
            l1 += __shfl_xor_sync(0xffffffffu, l1, o);
            l2 += __shfl_xor_sync(0xffffffffu, l2, o);
        }
        if (lane == 0) {
            l0 += sc3[0]; l1 += sc3[1]; l2 += sc3[2];
            float m   = fmaxf(l0, fmaxf(l1, l2));
            float e0  = expf(l0 - m), e1 = expf(l1 - m), e2 = expf(l2 - m);
            float inv = 1.f / (e0 + e1 + e2);
            sAlpha[0][t] = e0 * inv;
            sAlpha[1][t] = e1 * inv;
            sAlpha[2][t] = e2 * inv;
        }
    }
    __syncthreads();

    // ---- per-thread A-produce context: token tA, k-quarter kqA ----
    const int tA  = tid >> 2;
    const int kqA = (tid & 3) << 4;
    const size_t idA = (size_t)sIds[tA];
    const float* pa0 = E0 + idA * K0;
    const float* pa1 = E1 + idA * K1;
    const float* pa2 = E2 + idA * K2;
    const float aA0 = sAlpha[0][tA];
    const float aA1 = sAlpha[1][tA];
    const float aA2 = sAlpha[2][tA];

    auto fetchA = [&](int k) -> float {
        if (k < K0)       return pa0[k]        * aA0;
        else if (k < 600) return pa1[k - 300]  * aA1;
        else if (k < 800) return pa2[k - 600]  * aA2;
        return 0.f;
    };
    auto produceA = [&](int c, int stage) {
        const int kb = c * 64 + kqA;
        uint32_t w[8];
        #pragma unroll
        for (int jj = 0; jj < 16; jj += 2)
            w[jj >> 1] = pack_h2(fetchA(kb + jj), fetchA(kb + jj + 1));
        const uint32_t dst = sb + stage * A_STAGE + (tA * SPITCH + kqA) * 2;
        asm volatile("st.shared.v4.b32 [%0], {%1,%2,%3,%4};"
                     :: "r"(dst), "r"(w[0]), "r"(w[1]), "r"(w[2]), "r"(w[3]) : "memory");
        asm volatile("st.shared.v4.b32 [%0], {%1,%2,%3,%4};"
                     :: "r"(dst + 16), "r"(w[4]), "r"(w[5]), "r"(w[6]), "r"(w[7]) : "memory");
    };

    produceA(0, 0);
    produceA(1, 1);

    // ---- mainloop ----
    float acc[2][8][4];
    #pragma unroll
    for (int mt = 0; mt < 2; mt++)
        #pragma unroll
        for (int nt = 0; nt < 8; nt++)
            #pragma unroll
            for (int j = 0; j < 4; j++) acc[mt][nt][j] = 0.f;

    const int wm = (wid & 3) * 32;     // warp row base   (4 m-groups)
    const int wn = (wid >> 2) * 64;    // warp col base   (4 n-groups -> 256)
    const int lr = lane & 15;
    const int lc = lane >> 4;

    #pragma unroll 1
    for (int c = 0; c < NCHUNK; c++) {
        asm volatile("cp.async.wait_group %0;" :: "n"(STAGES - 2));
        __syncthreads();
        if (c + 2 < NCHUNK) {
            loadB(c + 2, (c + 2) % STAGES);
            produceA(c + 2, (c + 2) % STAGES);
        }

        const uint32_t As = sb  + (c % STAGES) * A_STAGE;
        const uint32_t Bs = sbB + (c % STAGES) * B_STAGE;

        #pragma unroll
        for (int ks = 0; ks < 4; ks++) {
            uint32_t a[2][4], b[4][4];
            #pragma unroll
            for (int mt = 0; mt < 2; mt++) {
                uint32_t addr = As + ((wm + mt*16 + lr) * SPITCH + ks*16 + lc*8) * 2;
                LDSM4(a[mt], addr);
            }
            #pragma unroll
            for (int nt2 = 0; nt2 < 4; nt2++) {
                uint32_t addr = Bs + ((wn + nt2*16 + lr) * SPITCH + ks*16 + lc*8) * 2;
                LDSM4(b[nt2], addr);
            }
            #pragma unroll
            for (int mt = 0; mt < 2; mt++)
                #pragma unroll
                for (int nt = 0; nt < 8; nt++) {
                    const int g = nt >> 1, h = nt & 1;
                    MMA16816(acc[mt][nt], a[mt], b[g][h], b[g][2 + h]);
                }
        }
    }

    // ---- epilogue: alpha-weighted bias + store ----
    #pragma unroll
    for (int mt = 0; mt < 2; mt++) {
        #pragma unroll
        for (int half = 0; half < 2; half++) {
            const int r  = wm + mt*16 + (lane >> 2) + half*8;
            const float a0 = sAlpha[0][r], a1 = sAlpha[1][r], a2 = sAlpha[2][r];
            float* orow = out + (size_t)(m0 + r) * DOUT;
            #pragma unroll
            for (int nt = 0; nt < 8; nt++) {
                const int cidx = wn + nt*8 + (lane & 3)*2;
                float2 v;
                v.x = acc[mt][nt][half*2 + 0]
                    + a0*sBias[0][cidx]   + a1*sBias[1][cidx]   + a2*sBias[2][cidx];
                v.y = acc[mt][nt][half*2 + 1]
                    + a0*sBias[0][cidx+1] + a1*sBias[1][cidx+1] + a2*sBias[2][cidx+1];
                *(float2*)(orow + cidx) = v;
            }
        }
    }
}

// ---------------------------------------------------------------------------
extern "C" void kernel_launch(void* const* d_in, const int* in_sizes, int n_in,
                              void* d_out, int out_size)
{
    const int*   ids = (const int*)  d_in[0];
    const float* E0  = (const float*)d_in[1];
    const float* E1  = (const float*)d_in[2];
    const float* E2  = (const float*)d_in[3];
    const float* W0  = (const float*)d_in[4];
    const float* b0  = (const float*)d_in[5];
    const float* W1  = (const float*)d_in[6];
    const float* b1  = (const float*)d_in[7];
    const float* W2  = (const float*)d_in[8];
    const float* b2  = (const float*)d_in[9];
    const float* Wa  = (const float*)d_in[10];
    const float* ba  = (const float*)d_in[11];
    float* out = (float*)d_out;

    // Idempotent, host-side, enqueues nothing (safe under graph capture).
    cudaFuncSetAttribute(fused_kernel, cudaFuncAttributeMaxDynamicSharedMemorySize, DYN_SMEM);

    prepw_kernel<<<520, 256>>>(W0, b0, W1, b1, W2, b2, Wa, ba);
    fused_kernel<<<BT / BM, 512, DYN_SMEM>>>(ids, E0, E1, E2, b0, b1, b2, out);
}

// round 13
// speedup vs baseline: 1.0941x; 1.0941x over previous
#include <cuda_runtime.h>
#include <cuda_fp16.h>
#include <cstdint>

// ---------------------------------------------------------------------------
// Problem constants
// ---------------------------------------------------------------------------
#define BT     16384          // B*T tokens
#define DOUT   256
#define K0     300
#define K1     300
#define K2     200
#define KTOT   800
#define KPAD   832            // 13 * 64, zero padded
#define NCHUNK 13

// GEMM tiling: one CTA = 128 tokens x all 256 outputs, 512 threads, 1 wave.
#define BM 128
#define BN 256
#define STAGES 3
#define SPITCH 72                        // fp16 elems per smem row (64 + 8 pad)
#define A_STAGE (BM * SPITCH * 2)        // 18432 B
#define B_STAGE (BN * SPITCH * 2)        // 36864 B
#define DYN_SMEM (STAGES * (A_STAGE + B_STAGE))   // 165888 B

// ---------------------------------------------------------------------------
// Device-global scratch (no allocations allowed)
// ---------------------------------------------------------------------------
__device__ float g_u[KTOT];
__device__ float g_c[3];
__device__ float g_alpha[BT * 3];
__device__ __align__(16) __half g_Ah[(size_t)BT * KPAD];     // alpha-scaled gathered A, fp16
__device__ __align__(16) __half g_Wh[(size_t)DOUT * KPAD];   // [n][k] (W transposed), fp16

// ---------------------------------------------------------------------------
// Helpers
// ---------------------------------------------------------------------------
__device__ __forceinline__ uint32_t su32(const void* p) {
    uint32_t a;
    asm("{ .reg .u64 t; cvta.to.shared.u64 t, %1; cvt.u32.u64 %0, t; }" : "=r"(a) : "l"(p));
    return a;
}
__device__ __forceinline__ void cpa16(uint32_t dst, const void* src) {
    asm volatile("cp.async.cg.shared.global [%0], [%1], 16;" :: "r"(dst), "l"(src) : "memory");
}
#define LDSM4(r, addr) \
    asm volatile("ldmatrix.sync.aligned.m8n8.x4.shared.b16 {%0,%1,%2,%3}, [%4];" \
                 : "=r"((r)[0]), "=r"((r)[1]), "=r"((r)[2]), "=r"((r)[3]) : "r"(addr))
#define MMA16816(d, a, bb0, bb1) \
    asm volatile("mma.sync.aligned.m16n8k16.row.col.f32.f16.f16.f32 " \
                 "{%0,%1,%2,%3}, {%4,%5,%6,%7}, {%8,%9}, {%0,%1,%2,%3};" \
                 : "+f"((d)[0]), "+f"((d)[1]), "+f"((d)[2]), "+f"((d)[3]) \
                 : "r"((a)[0]), "r"((a)[1]), "r"((a)[2]), "r"((a)[3]), "r"(bb0), "r"(bb1))

__device__ __forceinline__ uint32_t pack_h2(float v0, float v1) {
    __half2 h = __floats2half2_rn(v0, v1);
    return *reinterpret_cast<uint32_t*>(&h);
}

// ---------------------------------------------------------------------------
// Kernel 1 (unchanged, known-good): u = concat(W)@Wa, c = b.Wa + ba,
// W -> Wh^T fp16.  blocks [0,104): prep.  blocks [104,520): W convert.
// ---------------------------------------------------------------------------
__global__ void prepw_kernel(const float* __restrict__ W0, const float* __restrict__ b0,
                             const float* __restrict__ W1, const float* __restrict__ b1,
                             const float* __restrict__ W2, const float* __restrict__ b2,
                             const float* __restrict__ Wa, const float* __restrict__ ba)
{
    const int tid = threadIdx.x;
    if (blockIdx.x < 104) {
        int warp = blockIdx.x * 8 + (tid >> 5);
        int lane = tid & 31;
        if (warp < KTOT) {
            const float* row;
            if (warp < K0)           row = W0 + (size_t)warp * DOUT;
            else if (warp < K0+K1)   row = W1 + (size_t)(warp - K0) * DOUT;
            else                     row = W2 + (size_t)(warp - K0 - K1) * DOUT;
            float s = 0.f;
            for (int d = lane; d < DOUT; d += 32) s += row[d] * Wa[d];
            #pragma unroll
            for (int o = 16; o; o >>= 1) s += __shfl_xor_sync(0xffffffffu, s, o);
            if (lane == 0) g_u[warp] = s;
        } else if (warp < KTOT + 3) {
            int n = warp - KTOT;
            const float* b = (n == 0) ? b0 : ((n == 1) ? b1 : b2);
            float s = 0.f;
            for (int d = lane; d < DOUT; d += 32) s += b[d] * Wa[d];
            #pragma unroll
            for (int o = 16; o; o >>= 1) s += __shfl_xor_sync(0xffffffffu, s, o);
            if (lane == 0) g_c[n] = s + ba[0];
        }
    } else {
        int idx = (blockIdx.x - 104) * 256 + tid;
        if (idx < DOUT * (KPAD/2)) {
            int n  = idx / (KPAD/2);
            int k  = (idx % (KPAD/2)) * 2;
            float v0 = 0.f, v1 = 0.f;
            if (k < K0)        { v0 = W0[(size_t)k*DOUT + n];       v1 = W0[(size_t)(k+1)*DOUT + n]; }
            else if (k < 600)  { v0 = W1[(size_t)(k-300)*DOUT + n]; v1 = W1[(size_t)(k-299)*DOUT + n]; }
            else if (k < 800)  { v0 = W2[(size_t)(k-600)*DOUT + n]; v1 = W2[(size_t)(k-599)*DOUT + n]; }
            size_t off = ((size_t)n * KPAD + k) * 2;
            *(uint32_t*)((char*)g_Wh + off) = pack_h2(v0, v1);
        }
    }
}

// ---------------------------------------------------------------------------
// Kernel 2 (unchanged, known-good): logits -> softmax alphas, alpha-scaled
// fp16 A (row-major). One warp per token; high occupancy for the gather.
// ---------------------------------------------------------------------------
__global__ void alpha_split_kernel(const int* __restrict__ ids,
                                   const float* __restrict__ E0,
                                   const float* __restrict__ E1,
                                   const float* __restrict__ E2)
{
    __shared__ float su[KTOT];
    __shared__ float sc[3];
    for (int i = threadIdx.x; i < KTOT; i += blockDim.x) su[i] = g_u[i];
    if (threadIdx.x < 3) sc[threadIdx.x] = g_c[threadIdx.x];
    __syncthreads();

    const int warp = blockIdx.x * 8 + (threadIdx.x >> 5);   // token id
    const int lane = threadIdx.x & 31;
    const size_t id = (size_t)ids[warp];

    const float* r0 = E0 + id * K0;
    const float* r1 = E1 + id * K1;
    const float* r2 = E2 + id * K2;

    float l0 = 0.f, l1 = 0.f, l2 = 0.f;
    for (int k = lane; k < K0; k += 32) l0 += r0[k] * su[k];
    for (int k = lane; k < K1; k += 32) l1 += r1[k] * su[K0 + k];
    for (int k = lane; k < K2; k += 32) l2 += r2[k] * su[K0 + K1 + k];
    #pragma unroll
    for (int o = 16; o; o >>= 1) {
        l0 += __shfl_xor_sync(0xffffffffu, l0, o);
        l1 += __shfl_xor_sync(0xffffffffu, l1, o);
        l2 += __shfl_xor_sync(0xffffffffu, l2, o);
    }
    l0 += sc[0]; l1 += sc[1]; l2 += sc[2];
    float m   = fmaxf(l0, fmaxf(l1, l2));
    float e0  = expf(l0 - m), e1 = expf(l1 - m), e2 = expf(l2 - m);
    float inv = 1.f / (e0 + e1 + e2);
    float a0 = e0 * inv, a1 = e1 * inv, a2 = e2 * inv;
    if (lane == 0) {
        g_alpha[warp*3 + 0] = a0;
        g_alpha[warp*3 + 1] = a1;
        g_alpha[warp*3 + 2] = a2;
    }

    #pragma unroll 1
    for (int c = 0; c < NCHUNK; c++) {
        int k = c * 64 + lane * 2;
        float v0 = 0.f, v1 = 0.f;
        if (k < K0)        { v0 = r0[k] * a0;       v1 = r0[k+1] * a0; }
        else if (k < 600)  { v0 = r1[k-300] * a1;   v1 = r1[k-299] * a1; }
        else if (k < 800)  { v0 = r2[k-600] * a2;   v1 = r2[k-599] * a2; }
        size_t off = ((size_t)warp * KPAD + k) * 2;
        *(uint32_t*)((char*)g_Ah + off) = pack_h2(v0, v1);
    }
}

// ---------------------------------------------------------------------------
// Kernel 3: HMMA GEMM, one CTA per 128-token block covering ALL 256 outputs.
// A read once (cp.async from L2-resident g_Ah), B broadcast from L2.
// 512 threads, 16 warps (4m x 4n), warp tile 32x64, 3-stage pipeline, 1 wave.
// ---------------------------------------------------------------------------
__global__ void __launch_bounds__(512, 1)
gemm_kernel(const float* __restrict__ b0, const float* __restrict__ b1,
            const float* __restrict__ b2, float* __restrict__ out)
{
    extern __shared__ __align__(16) __half smem[];
    __shared__ float sBias[3][BN];
    __shared__ float sAl[3][BM];

    const int tid  = threadIdx.x;
    const int wid  = tid >> 5;
    const int lane = tid & 31;
    const int m0   = blockIdx.x * BM;

    for (int i = tid; i < BN; i += 512) {
        sBias[0][i] = b0[i];
        sBias[1][i] = b1[i];
        sBias[2][i] = b2[i];
    }
    if (tid < BM) {
        int t = m0 + tid;
        sAl[0][tid] = g_alpha[t*3 + 0];
        sAl[1][tid] = g_alpha[t*3 + 1];
        sAl[2][tid] = g_alpha[t*3 + 2];
    }
    __syncthreads();

    const uint32_t sb  = su32(smem);
    const uint32_t sbB = sb + STAGES * A_STAGE;

    // ---- pipelined load of one k-chunk stage (A: 2 / B: 4 cp.async per thr) ----
    auto loadStage = [&](int c, int stage) {
        const char* Ag = (const char*)g_Ah + (size_t)m0 * (KPAD*2) + c * 128;
        const char* Bg = (const char*)g_Wh + c * 128;
        const uint32_t As = sb  + stage * A_STAGE;
        const uint32_t Bs = sbB + stage * B_STAGE;
        #pragma unroll
        for (int i = 0; i < 2; i++) {
            int idx = tid + i * 512;
            int row = idx >> 3, cc = idx & 7;
            cpa16(As + (row * SPITCH + cc * 8) * 2, Ag + (size_t)row * (KPAD*2) + cc * 16);
        }
        #pragma unroll
        for (int i = 0; i < 4; i++) {
            int idx = tid + i * 512;
            int row = idx >> 3, cc = idx & 7;
            cpa16(Bs + (row * SPITCH + cc * 8) * 2, Bg + (size_t)row * (KPAD*2) + cc * 16);
        }
        asm volatile("cp.async.commit_group;" ::: "memory");
    };

    float acc[2][8][4];
    #pragma unroll
    for (int mt = 0; mt < 2; mt++)
        #pragma unroll
        for (int nt = 0; nt < 8; nt++)
            #pragma unroll
            for (int j = 0; j < 4; j++) acc[mt][nt][j] = 0.f;

    const int wm = (wid & 3) * 32;     // warp row base (4 m-groups)
    const int wn = (wid >> 2) * 64;    // warp col base (4 n-groups -> 256)
    const int lr = lane & 15;
    const int lc = lane >> 4;

    loadStage(0, 0);
    loadStage(1, 1);

    #pragma unroll 1
    for (int c = 0; c < NCHUNK; c++) {
        asm volatile("cp.async.wait_group %0;" :: "n"(STAGES - 2));
        __syncthreads();
        if (c + 2 < NCHUNK)
            loadStage(c + 2, (c + 2) % STAGES);

        const uint32_t As = sb  + (c % STAGES) * A_STAGE;
        const uint32_t Bs = sbB + (c % STAGES) * B_STAGE;

        #pragma unroll
        for (int ks = 0; ks < 4; ks++) {
            uint32_t a[2][4], b[4][4];
            #pragma unroll
            for (int mt = 0; mt < 2; mt++) {
                uint32_t addr = As + ((wm + mt*16 + lr) * SPITCH + ks*16 + lc*8) * 2;
                LDSM4(a[mt], addr);
            }
            #pragma unroll
            for (int nt2 = 0; nt2 < 4; nt2++) {
                uint32_t addr = Bs + ((wn + nt2*16 + lr) * SPITCH + ks*16 + lc*8) * 2;
                LDSM4(b[nt2], addr);
            }
            #pragma unroll
            for (int mt = 0; mt < 2; mt++)
                #pragma unroll
                for (int nt = 0; nt < 8; nt++) {
                    const int g = nt >> 1, h = nt & 1;
                    MMA16816(acc[mt][nt], a[mt], b[g][h], b[g][2 + h]);
                }
        }
    }

    // ---- epilogue: alpha-weighted bias + store ----
    #pragma unroll
    for (int mt = 0; mt < 2; mt++) {
        #pragma unroll
        for (int half = 0; half < 2; half++) {
            const int r  = wm + mt*16 + (lane >> 2) + half*8;
            const float a0 = sAl[0][r], a1 = sAl[1][r], a2 = sAl[2][r];
            float* orow = out + (size_t)(m0 + r) * DOUT;
            #pragma unroll
            for (int nt = 0; nt < 8; nt++) {
                const int cidx = wn + nt*8 + (lane & 3)*2;
                float2 v;
                v.x = acc[mt][nt][half*2 + 0]
                    + a0*sBias[0][cidx]   + a1*sBias[1][cidx]   + a2*sBias[2][cidx];
                v.y = acc[mt][nt][half*2 + 1]
                    + a0*sBias[0][cidx+1] + a1*sBias[1][cidx+1] + a2*sBias[2][cidx+1];
                *(float2*)(orow + cidx) = v;
            }
        }
    }
}

// ---------------------------------------------------------------------------
extern "C" void kernel_launch(void* const* d_in, const int* in_sizes, int n_in,
                              void* d_out, int out_size)
{
    const int*   ids = (const int*)  d_in[0];
    const float* E0  = (const float*)d_in[1];
    const float* E1  = (const float*)d_in[2];
    const float* E2  = (const float*)d_in[3];
    const float* W0  = (const float*)d_in[4];
    const float* b0  = (const float*)d_in[5];
    const float* W1  = (const float*)d_in[6];
    const float* b1  = (const float*)d_in[7];
    const float* W2  = (const float*)d_in[8];
    const float* b2  = (const float*)d_in[9];
    const float* Wa  = (const float*)d_in[10];
    const float* ba  = (const float*)d_in[11];
    float* out = (float*)d_out;

    // Idempotent, host-side, enqueues nothing (safe under graph capture).
    cudaFuncSetAttribute(gemm_kernel, cudaFuncAttributeMaxDynamicSharedMemorySize, DYN_SMEM);

    prepw_kernel<<<520, 256>>>(W0, b0, W1, b1, W2, b2, Wa, ba);
    alpha_split_kernel<<<BT / 8, 256>>>(ids, E0, E1, E2);
    gemm_kernel<<<BT / BM, 512, DYN_SMEM>>>(b0, b1, b2, out);
}

// round 15
// speedup vs baseline: 1.2434x; 1.1364x over previous
#include <cuda_runtime.h>
#include <cuda_fp16.h>
#include <cstdint>

// ---------------------------------------------------------------------------
// Problem constants
// ---------------------------------------------------------------------------
#define BT     16384          // B*T tokens
#define DOUT   256
#define K0     300
#define K1     300
#define K2     200
#define KTOT   800
#define KPAD   832            // 13 * 64, zero padded
#define NCHUNK 13

// GEMM tiling: one CTA = 128 tokens x all 256 outputs, 512 threads, 1 wave.
#define BM 128
#define BN 256
#define STAGES 3
#define SPITCH 72                        // fp16 elems per smem row (64 + 8 pad)
#define A_STAGE (BM * SPITCH * 2)        // 18432 B
#define B_STAGE (BN * SPITCH * 2)        // 36864 B
#define DYN_SMEM (STAGES * (A_STAGE + B_STAGE))   // 165888 B

// ---------------------------------------------------------------------------
// Device-global scratch (no allocations allowed)
// ---------------------------------------------------------------------------
__device__ float g_u[KTOT];
__device__ float g_c[3];
__device__ float g_alpha[BT * 3];
__device__ __align__(16) __half g_Ah[(size_t)BT * KPAD];     // alpha-scaled gathered A, fp16
__device__ __align__(16) __half g_Wh[(size_t)DOUT * KPAD];   // [n][k] (W transposed), fp16

// ---------------------------------------------------------------------------
// Helpers
// ---------------------------------------------------------------------------
__device__ __forceinline__ uint32_t su32(const void* p) {
    uint32_t a;
    asm("{ .reg .u64 t; cvta.to.shared.u64 t, %1; cvt.u32.u64 %0, t; }" : "=r"(a) : "l"(p));
    return a;
}
__device__ __forceinline__ void cpa16(uint32_t dst, const void* src) {
    asm volatile("cp.async.cg.shared.global [%0], [%1], 16;" :: "r"(dst), "l"(src) : "memory");
}
#define LDSM4(r, addr) \
    asm volatile("ldmatrix.sync.aligned.m8n8.x4.shared.b16 {%0,%1,%2,%3}, [%4];" \
                 : "=r"((r)[0]), "=r"((r)[1]), "=r"((r)[2]), "=r"((r)[3]) : "r"(addr))
#define MMA16816(d, a, bb0, bb1) \
    asm volatile("mma.sync.aligned.m16n8k16.row.col.f32.f16.f16.f32 " \
                 "{%0,%1,%2,%3}, {%4,%5,%6,%7}, {%8,%9}, {%0,%1,%2,%3};" \
                 : "+f"((d)[0]), "+f"((d)[1]), "+f"((d)[2]), "+f"((d)[3]) \
                 : "r"((a)[0]), "r"((a)[1]), "r"((a)[2]), "r"((a)[3]), "r"(bb0), "r"(bb1))

__device__ __forceinline__ uint32_t pack_h2(float v0, float v1) {
    __half2 h = __floats2half2_rn(v0, v1);
    return *reinterpret_cast<uint32_t*>(&h);
}

// ---------------------------------------------------------------------------
// Kernel 1: u = concat(W)@Wa, c = b.Wa + ba.  101 blocks x 256 (808 warps).
// float4-vectorized dot: 2 LDG.128 per lane.
// ---------------------------------------------------------------------------
__global__ void prep_u_kernel(const float* __restrict__ W0, const float* __restrict__ b0,
                              const float* __restrict__ W1, const float* __restrict__ b1,
                              const float* __restrict__ W2, const float* __restrict__ b2,
                              const float* __restrict__ Wa, const float* __restrict__ ba)
{
    const int warp = blockIdx.x * 8 + (threadIdx.x >> 5);
    const int lane = threadIdx.x & 31;

    const float* row = nullptr;
    if (warp < K0)            row = W0 + (size_t)warp * DOUT;
    else if (warp < K0+K1)    row = W1 + (size_t)(warp - K0) * DOUT;
    else if (warp < KTOT)     row = W2 + (size_t)(warp - K0 - K1) * DOUT;
    else if (warp < KTOT + 3) {
        int n = warp - KTOT;
        row = (n == 0) ? b0 : ((n == 1) ? b1 : b2);
    } else return;

    const float4 p = *(const float4*)(row + lane * 8);
    const float4 q = *(const float4*)(row + lane * 8 + 4);
    const float4 wp = *(const float4*)(Wa + lane * 8);
    const float4 wq = *(const float4*)(Wa + lane * 8 + 4);
    float s = p.x*wp.x + p.y*wp.y + p.z*wp.z + p.w*wp.w
            + q.x*wq.x + q.y*wq.y + q.z*wq.z + q.w*wq.w;
    #pragma unroll
    for (int o = 16; o; o >>= 1) s += __shfl_xor_sync(0xffffffffu, s, o);
    if (lane == 0) {
        if (warp < KTOT) g_u[warp] = s;
        else             g_c[warp - KTOT] = s + ba[0];
    }
}

// ---------------------------------------------------------------------------
// Kernel 2: blocks [0,2048): one warp per token — single-pass logits+softmax+
// alpha-scaled fp16 A (register-resident, float4 loads, E read ONCE).
// blocks [2048,2061): W -> Wh^T fp16, coalesced reads + dense per-thread rows.
// ---------------------------------------------------------------------------
__global__ void alpha_split_kernel(const int* __restrict__ ids,
                                   const float* __restrict__ E0,
                                   const float* __restrict__ E1,
                                   const float* __restrict__ E2,
                                   const float* __restrict__ W0,
                                   const float* __restrict__ W1,
                                   const float* __restrict__ W2)
{
    if (blockIdx.x >= 2048) {
        // ---- W convert: chunk c, thread = output column n ----
        const int c = blockIdx.x - 2048;    // 0..12
        const int n = threadIdx.x;          // 0..255
        uint32_t packed[32];
        #pragma unroll
        for (int p = 0; p < 32; p++) {
            const int k0 = c * 64 + p * 2;
            const int k1 = k0 + 1;
            float v0 = 0.f, v1 = 0.f;
            if (k0 < K0)       v0 = W0[(size_t)k0 * DOUT + n];
            else if (k0 < 600) v0 = W1[(size_t)(k0-300) * DOUT + n];
            else if (k0 < 800) v0 = W2[(size_t)(k0-600) * DOUT + n];
            if (k1 < K0)       v1 = W0[(size_t)k1 * DOUT + n];
            else if (k1 < 600) v1 = W1[(size_t)(k1-300) * DOUT + n];
            else if (k1 < 800) v1 = W2[(size_t)(k1-600) * DOUT + n];
            packed[p] = pack_h2(v0, v1);
        }
        uint32_t* dst = (uint32_t*)((char*)g_Wh + ((size_t)n * KPAD + c * 64) * 2);
        #pragma unroll
        for (int p = 0; p < 32; p += 4)
            *(uint4*)(dst + p) = make_uint4(packed[p], packed[p+1], packed[p+2], packed[p+3]);
        return;
    }

    __shared__ float su[896];     // u padded with zeros to 896 (k up to 892 read)
    __shared__ float sc[3];
    for (int i = threadIdx.x; i < 896; i += 256) su[i] = (i < KTOT) ? g_u[i] : 0.f;
    if (threadIdx.x < 3) sc[threadIdx.x] = g_c[threadIdx.x];
    __syncthreads();

    const int warp = blockIdx.x * 8 + (threadIdx.x >> 5);   // token id
    const int lane = threadIdx.x & 31;
    const size_t id = (size_t)ids[warp];

    const float* r0 = E0 + id * K0;
    const float* r1 = E1 + id * K1;
    const float* r2 = E2 + id * K2;

    // ---- single pass: load 7 float4s (28 elems), dot with u, keep in regs ----
    float4 e[7];
    float l0 = 0.f, l1 = 0.f, l2 = 0.f;
    #pragma unroll
    for (int c = 0; c < 7; c++) {
        const int k = c * 128 + lane * 4;
        float4 v;
        if (k < K0)       v = *(const float4*)(r0 + k);
        else if (k < 600) v = *(const float4*)(r1 + k - 300);
        else if (k < 800) v = *(const float4*)(r2 + k - 600);
        else              v = make_float4(0.f, 0.f, 0.f, 0.f);
        e[c] = v;
        const float4 u4 = *(const float4*)(su + k);
        const float d = v.x*u4.x + v.y*u4.y + v.z*u4.z + v.w*u4.w;
        if (k < K0)       l0 += d;
        else if (k < 600) l1 += d;
        else              l2 += d;
    }
    #pragma unroll
    for (int o = 16; o; o >>= 1) {
        l0 += __shfl_xor_sync(0xffffffffu, l0, o);
        l1 += __shfl_xor_sync(0xffffffffu, l1, o);
        l2 += __shfl_xor_sync(0xffffffffu, l2, o);
    }
    // xor-reduce leaves full sums in every lane: softmax computed redundantly.
    l0 += sc[0]; l1 += sc[1]; l2 += sc[2];
    const float m   = fmaxf(l0, fmaxf(l1, l2));
    const float x0  = expf(l0 - m), x1 = expf(l1 - m), x2 = expf(l2 - m);
    const float inv = 1.f / (x0 + x1 + x2);
    const float a0 = x0 * inv, a1 = x1 * inv, a2 = x2 * inv;
    if (lane == 0) {
        g_alpha[warp*3 + 0] = a0;
        g_alpha[warp*3 + 1] = a1;
        g_alpha[warp*3 + 2] = a2;
    }

    // ---- scale registers, convert, write 8B/lane coalesced ----
    #pragma unroll
    for (int c = 0; c < 7; c++) {
        const int k = c * 128 + lane * 4;
        const float s = (k < K0) ? a0 : ((k < 600) ? a1 : a2);
        const uint32_t h0 = pack_h2(e[c].x * s, e[c].y * s);
        const uint32_t h1 = pack_h2(e[c].z * s, e[c].w * s);
        if (k < KPAD) {   // c<6 always; c==6 lanes 0..15 (zeros fill 800..831)
            uint32_t* dst = (uint32_t*)((char*)g_Ah + ((size_t)warp * KPAD + k) * 2);
            asm volatile("st.global.v2.b32 [%0], {%1,%2};" :: "l"(dst), "r"(h0), "r"(h1) : "memory");
        }
    }
}

// ---------------------------------------------------------------------------
// Kernel 3 (unchanged, known-good): HMMA GEMM, one CTA per 128-token block
// covering all 256 outputs. 512 threads, 16 warps (4m x 4n), 3-stage, 1 wave.
// ---------------------------------------------------------------------------
__global__ void __launch_bounds__(512, 1)
gemm_kernel(const float* __restrict__ b0, const float* __restrict__ b1,
            const float* __restrict__ b2, float* __restrict__ out)
{
    extern __shared__ __align__(16) __half smem[];
    __shared__ float sBias[3][BN];
    __shared__ float sAl[3][BM];

    const int tid  = threadIdx.x;
    const int wid  = tid >> 5;
    const int lane = tid & 31;
    const int m0   = blockIdx.x * BM;

    for (int i = tid; i < BN; i += 512) {
        sBias[0][i] = b0[i];
        sBias[1][i] = b1[i];
        sBias[2][i] = b2[i];
    }
    if (tid < BM) {
        int t = m0 + tid;
        sAl[0][tid] = g_alpha[t*3 + 0];
        sAl[1][tid] = g_alpha[t*3 + 1];
        sAl[2][tid] = g_alpha[t*3 + 2];
    }
    __syncthreads();

    const uint32_t sb  = su32(smem);
    const uint32_t sbB = sb + STAGES * A_STAGE;

    auto loadStage = [&](int c, int stage) {
        const char* Ag = (const char*)g_Ah + (size_t)m0 * (KPAD*2) + c * 128;
        const char* Bg = (const char*)g_Wh + c * 128;
        const uint32_t As = sb  + stage * A_STAGE;
        const uint32_t Bs = sbB + stage * B_STAGE;
        #pragma unroll
        for (int i = 0; i < 2; i++) {
            int idx = tid + i * 512;
            int row = idx >> 3, cc = idx & 7;
            cpa16(As + (row * SPITCH + cc * 8) * 2, Ag + (size_t)row * (KPAD*2) + cc * 16);
        }
        #pragma unroll
        for (int i = 0; i < 4; i++) {
            int idx = tid + i * 512;
            int row = idx >> 3, cc = idx & 7;
            cpa16(Bs + (row * SPITCH + cc * 8) * 2, Bg + (size_t)row * (KPAD*2) + cc * 16);
        }
        asm volatile("cp.async.commit_group;" ::: "memory");
    };

    float acc[2][8][4];
    #pragma unroll
    for (int mt = 0; mt < 2; mt++)
        #pragma unroll
        for (int nt = 0; nt < 8; nt++)
            #pragma unroll
            for (int j = 0; j < 4; j++) acc[mt][nt][j] = 0.f;

    const int wm = (wid & 3) * 32;
    const int wn = (wid >> 2) * 64;
    const int lr = lane & 15;
    const int lc = lane >> 4;

    loadStage(0, 0);
    loadStage(1, 1);

    #pragma unroll 1
    for (int c = 0; c < NCHUNK; c++) {
        asm volatile("cp.async.wait_group %0;" :: "n"(STAGES - 2));
        __syncthreads();
        if (c + 2 < NCHUNK)
            loadStage(c + 2, (c + 2) % STAGES);

        const uint32_t As = sb  + (c % STAGES) * A_STAGE;
        const uint32_t Bs = sbB + (c % STAGES) * B_STAGE;

        #pragma unroll
        for (int ks = 0; ks < 4; ks++) {
            uint32_t a[2][4], b[4][4];
            #pragma unroll
            for (int mt = 0; mt < 2; mt++) {
                uint32_t addr = As + ((wm + mt*16 + lr) * SPITCH + ks*16 + lc*8) * 2;
                LDSM4(a[mt], addr);
            }
            #pragma unroll
            for (int nt2 = 0; nt2 < 4; nt2++) {
                uint32_t addr = Bs + ((wn + nt2*16 + lr) * SPITCH + ks*16 + lc*8) * 2;
                LDSM4(b[nt2], addr);
            }
            #pragma unroll
            for (int mt = 0; mt < 2; mt++)
                #pragma unroll
                for (int nt = 0; nt < 8; nt++) {
                    const int g = nt >> 1, h = nt & 1;
                    MMA16816(acc[mt][nt], a[mt], b[g][h], b[g][2 + h]);
                }
        }
    }

    #pragma unroll
    for (int mt = 0; mt < 2; mt++) {
        #pragma unroll
        for (int half = 0; half < 2; half++) {
            const int r  = wm + mt*16 + (lane >> 2) + half*8;
            const float a0 = sAl[0][r], a1 = sAl[1][r], a2 = sAl[2][r];
            float* orow = out + (size_t)(m0 + r) * DOUT;
            #pragma unroll
            for (int nt = 0; nt < 8; nt++) {
                const int cidx = wn + nt*8 + (lane & 3)*2;
                float2 v;
                v.x = acc[mt][nt][half*2 + 0]
                    + a0*sBias[0][cidx]   + a1*sBias[1][cidx]   + a2*sBias[2][cidx];
                v.y = acc[mt][nt][half*2 + 1]
                    + a0*sBias[0][cidx+1] + a1*sBias[1][cidx+1] + a2*sBias[2][cidx+1];
                *(float2*)(orow + cidx) = v;
            }
        }
    }
}

// ---------------------------------------------------------------------------
extern "C" void kernel_launch(void* const* d_in, const int* in_sizes, int n_in,
                              void* d_out, int out_size)
{
    const int*   ids = (const int*)  d_in[0];
    const float* E0  = (const float*)d_in[1];
    const float* E1  = (const float*)d_in[2];
    const float* E2  = (const float*)d_in[3];
    const float* W0  = (const float*)d_in[4];
    const float* b0  = (const float*)d_in[5];
    const float* W1  = (const float*)d_in[6];
    const float* b1  = (const float*)d_in[7];
    const float* W2  = (const float*)d_in[8];
    const float* b2  = (const float*)d_in[9];
    const float* Wa  = (const float*)d_in[10];
    const float* ba  = (const float*)d_in[11];
    float* out = (float*)d_out;

    // Idempotent, host-side, enqueues nothing (safe under graph capture).
    cudaFuncSetAttribute(gemm_kernel, cudaFuncAttributeMaxDynamicSharedMemorySize, DYN_SMEM);

    prep_u_kernel<<<101, 256>>>(W0, b0, W1, b1, W2, b2, Wa, ba);
    alpha_split_kernel<<<2048 + NCHUNK, 256>>>(ids, E0, E1, E2, W0, W1, W2);
    gemm_kernel<<<BT / BM, 512, DYN_SMEM>>>(b0, b1, b2, out);
}